// round 2
// baseline (speedup 1.0000x reference)
#include <cuda_runtime.h>
#include <cstdint>
#include <math.h>

typedef unsigned long long u64;

// ---------------------------------------------------------------------------
// Packed f32x2 helpers (Blackwell sm_103a)
// ---------------------------------------------------------------------------
__device__ __forceinline__ u64 ffma2(u64 a, u64 b, u64 c) {
    u64 d;
    asm("fma.rn.f32x2 %0, %1, %2, %3;" : "=l"(d) : "l"(a), "l"(b), "l"(c));
    return d;
}
__device__ __forceinline__ u64 pack2(float x, float y) {
    u64 r;
    asm("mov.b64 %0, {%1, %2};" : "=l"(r) : "f"(x), "f"(y));
    return r;
}
__device__ __forceinline__ float2 unpack2(u64 v) {
    float2 f;
    asm("mov.b64 {%0, %1}, %2;" : "=f"(f.x), "=f"(f.y) : "l"(v));
    return f;
}
__device__ __forceinline__ uint32_t smem_u32(const void* p) {
    uint32_t a;
    asm("{ .reg .u64 t; cvta.to.shared.u64 t, %1; cvt.u32.u64 %0, t; }"
        : "=r"(a) : "l"(p));
    return a;
}

// Accurate tanh via ex2.approx (rel err ~2^-22) — tanhf would lower to
// tanh.approx (abs err ~2^-11) under fast-math and fail 1e-3 over 1024 steps.
__device__ __forceinline__ float tanh_acc(float x) {
    float e = __expf(2.0f * x);
    return 1.0f - 2.0f / (e + 1.0f);
}

// ---------------------------------------------------------------------------
// Phase 1: x_proj GEMM (unchanged from R1; 231us, ~50% of fp32 peak)
// ---------------------------------------------------------------------------
__global__ void __launch_bounds__(256) xproj_kernel(
    const float* __restrict__ X, const float* __restrict__ Wih,
    const float* __restrict__ bih, float* __restrict__ C)
{
    __shared__ __align__(16) float As[16][128];
    __shared__ __align__(16) float Bs[16][128];

    const int tid = threadIdx.x;
    const int tx  = tid & 15;
    const int ty  = tid >> 4;
    const int m0  = blockIdx.y * 128;
    const int n0  = blockIdx.x * 128;

    u64 acc[8][4];
#pragma unroll
    for (int m = 0; m < 8; m++)
#pragma unroll
        for (int n = 0; n < 4; n++) acc[m][n] = 0ull;

    for (int k0 = 0; k0 < 256; k0 += 16) {
#pragma unroll
        for (int i = 0; i < 2; i++) {
            int idx = tid + i * 256;
            int row = idx >> 2;
            int kq  = (idx & 3) << 2;
            float4 xa = *(const float4*)(X + (size_t)(m0 + row) * 256 + k0 + kq);
            As[kq + 0][row] = xa.x; As[kq + 1][row] = xa.y;
            As[kq + 2][row] = xa.z; As[kq + 3][row] = xa.w;
            float4 wa = *(const float4*)(Wih + (size_t)(n0 + row) * 256 + k0 + kq);
            Bs[kq + 0][row] = wa.x; Bs[kq + 1][row] = wa.y;
            Bs[kq + 2][row] = wa.z; Bs[kq + 3][row] = wa.w;
        }
        __syncthreads();

#pragma unroll
        for (int kk = 0; kk < 16; kk++) {
            float4 a0 = *(const float4*)&As[kk][ty * 8];
            float4 a1 = *(const float4*)&As[kk][ty * 8 + 4];
            float4 b0 = *(const float4*)&Bs[kk][tx * 8];
            float4 b1 = *(const float4*)&Bs[kk][tx * 8 + 4];
            u64 bb[4] = { pack2(b0.x, b0.y), pack2(b0.z, b0.w),
                          pack2(b1.x, b1.y), pack2(b1.z, b1.w) };
            float am[8] = { a0.x, a0.y, a0.z, a0.w, a1.x, a1.y, a1.z, a1.w };
#pragma unroll
            for (int m = 0; m < 8; m++) {
                u64 ad = pack2(am[m], am[m]);
#pragma unroll
                for (int n = 0; n < 4; n++) acc[m][n] = ffma2(ad, bb[n], acc[m][n]);
            }
        }
        __syncthreads();
    }

    const int nc = n0 + tx * 8;
    float4 bv0 = *(const float4*)(bih + nc);
    float4 bv1 = *(const float4*)(bih + nc + 4);
#pragma unroll
    for (int m = 0; m < 8; m++) {
        float2 r0 = unpack2(acc[m][0]), r1 = unpack2(acc[m][1]);
        float2 r2 = unpack2(acc[m][2]), r3 = unpack2(acc[m][3]);
        float* cp = C + (size_t)(m0 + ty * 8 + m) * 256 + nc;
        *(float4*)cp       = make_float4(r0.x + bv0.x, r0.y + bv0.y,
                                         r1.x + bv0.z, r1.y + bv0.w);
        *(float4*)(cp + 4) = make_float4(r2.x + bv1.x, r2.y + bv1.y,
                                         r3.x + bv1.z, r3.y + bv1.w);
    }
}

// ---------------------------------------------------------------------------
// Phase 2 (v2): symmetric partial-sum exchange.
// One 2-CTA cluster per batch row. CTA rank r, thread j (0..255):
//   holds W_hh[j][r*128 .. r*128+127] in 64 packed f32x2 registers.
// Per step: every thread computes its k-half partial for output j, ships it
// to the peer CTA (v4-packed DSMEM store + count-4 mbarrier arrive from every
// 4th lane), then BOTH CTAs redundantly combine + tanh all 256 outputs.
// h never crosses the cluster; one __syncthreads per step.
// ---------------------------------------------------------------------------
__device__ __forceinline__ void mbar_wait_cluster(uint32_t addr, uint32_t parity) {
    asm volatile(
        "{\n\t"
        ".reg .pred P;\n\t"
        "LAB_W_%=:\n\t"
        "mbarrier.try_wait.parity.acquire.cluster.shared::cta.b64 P, [%0], %1, 0x989680;\n\t"
        "@P bra.uni LAB_D_%=;\n\t"
        "bra.uni LAB_W_%=;\n\t"
        "LAB_D_%=:\n\t"
        "}"
        :: "r"(addr), "r"(parity) : "memory");
}

__global__ void __cluster_dims__(2, 1, 1) __launch_bounds__(256, 1)
rnn_scan_kernel(const float* __restrict__ Whh, const float* __restrict__ bhh,
                float* __restrict__ out)
{
    __shared__ __align__(16) float h_sm[2][256];   // hidden state, step-parity buffered
    __shared__ __align__(16) float pp_sm[2][256];  // partials arriving from peer
    __shared__ __align__(8) u64 mbar;

    const int tid = threadIdx.x;
    uint32_t rank;
    asm("mov.u32 %0, %%cluster_ctarank;" : "=r"(rank));
    const int batch = blockIdx.x >> 1;
    const int j     = tid;                    // output index owned by this thread
    const int kbase = (int)rank * 128;        // this CTA's k-half

    // --- W_hh[j][kbase .. kbase+127] -> 64 packed f32x2 registers ---
    u64 w2[64];
    {
        const ulonglong2* wrow = (const ulonglong2*)(Whh + (size_t)j * 256 + kbase);
#pragma unroll
        for (int i = 0; i < 32; i++) {
            ulonglong2 v = wrow[i];
            w2[2 * i] = v.x; w2[2 * i + 1] = v.y;
        }
    }

    // --- init ---
    h_sm[0][tid] = 0.0f;
    h_sm[1][tid] = 0.0f;
    uint32_t mbar_a = smem_u32(&mbar);
    if (tid == 0)
        asm volatile("mbarrier.init.shared.b64 [%0], 256;" :: "r"(mbar_a) : "memory");
    asm volatile("barrier.cluster.arrive.aligned;" ::: "memory");
    asm volatile("barrier.cluster.wait.aligned;" ::: "memory");

    uint32_t pp_a = smem_u32(&pp_sm[0][0]);
    uint32_t peer = rank ^ 1u;
    uint32_t pp_peer, mbar_peer;
    asm("mapa.shared::cluster.u32 %0, %1, %2;" : "=r"(pp_peer)   : "r"(pp_a),   "r"(peer));
    asm("mapa.shared::cluster.u32 %0, %1, %2;" : "=r"(mbar_peer) : "r"(mbar_a), "r"(peer));

    float* outb = out + (size_t)batch * (1024 * 256) + j;   // column j
    const float bh = bhh[j];
    const bool writer = ((j >> 7) == (int)rank);            // who stores h[j] to gmem
    float xp_next = outb[0];                                // xp for t=0 (in-place buffer)

    for (int t = 0; t < 1024; t++) {
        const float xp_cur = xp_next;

        // --- partial dot over this CTA's k-half (broadcast LDS.128) ---
        const ulonglong2* h4 = (const ulonglong2*)&h_sm[t & 1][kbase];
        u64 acc0 = 0ull, acc1 = 0ull;
#pragma unroll
        for (int i = 0; i < 32; i += 2) {
            ulonglong2 va = h4[i];
            acc0 = ffma2(w2[2 * i],     va.x, acc0);
            acc1 = ffma2(w2[2 * i + 1], va.y, acc1);
            ulonglong2 vb = h4[i + 1];
            acc0 = ffma2(w2[2 * i + 2], vb.x, acc0);
            acc1 = ffma2(w2[2 * i + 3], vb.y, acc1);
        }
        float2 a0 = unpack2(acc0), a1 = unpack2(acc1);
        const float s = (a0.x + a0.y) + (a1.x + a1.y);

        // prefetch next timestep's xp while the exchange is in flight
        if (t < 1023) xp_next = __ldg(outb + (size_t)(t + 1) * 256);

        // --- ship partials to peer: pack 4 per lane, v4 DSMEM store, count-4 arrive ---
        const float s1 = __shfl_down_sync(0xFFFFFFFFu, s, 1);
        const float s2 = __shfl_down_sync(0xFFFFFFFFu, s, 2);
        const float s3 = __shfl_down_sync(0xFFFFFFFFu, s, 3);
        if ((tid & 3) == 0) {
            uint32_t raddr = pp_peer + (uint32_t)(((t & 1) << 8) + j) * 4u;
            asm volatile("st.shared::cluster.v4.f32 [%0], {%1, %2, %3, %4};"
                         :: "r"(raddr), "f"(s), "f"(s1), "f"(s2), "f"(s3) : "memory");
            asm volatile("mbarrier.arrive.release.cluster.shared::cluster.b64 _, [%0], 4;"
                         :: "r"(mbar_peer) : "memory");
        }

        // --- wait for peer's 256 partials of this step ---
        mbar_wait_cluster(mbar_a, (uint32_t)(t & 1));

        // --- redundant combine + tanh (every thread, its own j) ---
        const float tot = s + pp_sm[t & 1][j] + xp_cur + bh;
        const float h = tanh_acc(tot);
        h_sm[(t + 1) & 1][j] = h;
        if (writer) outb[(size_t)t * 256] = h;

        __syncthreads();   // all h_{t} writes visible before step t+1 reads
    }

    // keep smem alive until peer's in-flight DSMEM stores complete
    asm volatile("barrier.cluster.arrive.aligned;" ::: "memory");
    asm volatile("barrier.cluster.wait.aligned;" ::: "memory");
}

// ---------------------------------------------------------------------------
// Harness entry. Inputs: x, W_ih, W_hh, b_ih, b_hh. Output fp32 [B,T,H].
// x_proj is materialized into d_out, then overwritten in place by h_t.
// ---------------------------------------------------------------------------
extern "C" void kernel_launch(void* const* d_in, const int* in_sizes, int n_in,
                              void* d_out, int out_size)
{
    const float* x   = (const float*)d_in[0];
    const float* Wih = (const float*)d_in[1];
    const float* Whh = (const float*)d_in[2];
    const float* bih = (const float*)d_in[3];
    const float* bhh = (const float*)d_in[4];
    float* out = (float*)d_out;

    dim3 g1(2, 512);
    xproj_kernel<<<g1, 256>>>(x, Wih, bih, out);

    rnn_scan_kernel<<<128, 256>>>(Whh, bhh, out);
}

// round 4
// speedup vs baseline: 1.4178x; 1.4178x over previous
#include <cuda_runtime.h>
#include <cstdint>
#include <math.h>

typedef unsigned long long u64;

// ---------------------------------------------------------------------------
// Packed f32x2 helpers (Blackwell sm_103a)
// ---------------------------------------------------------------------------
__device__ __forceinline__ u64 ffma2(u64 a, u64 b, u64 c) {
    u64 d;
    asm("fma.rn.f32x2 %0, %1, %2, %3;" : "=l"(d) : "l"(a), "l"(b), "l"(c));
    return d;
}
__device__ __forceinline__ u64 pack2(float x, float y) {
    u64 r;
    asm("mov.b64 %0, {%1, %2};" : "=l"(r) : "f"(x), "f"(y));
    return r;
}
__device__ __forceinline__ float2 unpack2(u64 v) {
    float2 f;
    asm("mov.b64 {%0, %1}, %2;" : "=f"(f.x), "=f"(f.y) : "l"(v));
    return f;
}
__device__ __forceinline__ uint32_t smem_u32(const void* p) {
    uint32_t a;
    asm("{ .reg .u64 t; cvta.to.shared.u64 t, %1; cvt.u32.u64 %0, t; }"
        : "=r"(a) : "l"(p));
    return a;
}

// Accurate tanh via ex2.approx (rel err ~2^-22); tanhf under fast-math lowers
// to tanh.approx (abs err ~2^-11) and fails 1e-3 over 1024 recurrent steps.
__device__ __forceinline__ float tanh_acc(float x) {
    float e = __expf(2.0f * x);
    return 1.0f - 2.0f / (e + 1.0f);
}

// ---------------------------------------------------------------------------
// Phase 1: x_proj GEMM (unchanged; ~231us)
// ---------------------------------------------------------------------------
__global__ void __launch_bounds__(256) xproj_kernel(
    const float* __restrict__ X, const float* __restrict__ Wih,
    const float* __restrict__ bih, float* __restrict__ C)
{
    __shared__ __align__(16) float As[16][128];
    __shared__ __align__(16) float Bs[16][128];

    const int tid = threadIdx.x;
    const int tx  = tid & 15;
    const int ty  = tid >> 4;
    const int m0  = blockIdx.y * 128;
    const int n0  = blockIdx.x * 128;

    u64 acc[8][4];
#pragma unroll
    for (int m = 0; m < 8; m++)
#pragma unroll
        for (int n = 0; n < 4; n++) acc[m][n] = 0ull;

    for (int k0 = 0; k0 < 256; k0 += 16) {
#pragma unroll
        for (int i = 0; i < 2; i++) {
            int idx = tid + i * 256;
            int row = idx >> 2;
            int kq  = (idx & 3) << 2;
            float4 xa = *(const float4*)(X + (size_t)(m0 + row) * 256 + k0 + kq);
            As[kq + 0][row] = xa.x; As[kq + 1][row] = xa.y;
            As[kq + 2][row] = xa.z; As[kq + 3][row] = xa.w;
            float4 wa = *(const float4*)(Wih + (size_t)(n0 + row) * 256 + k0 + kq);
            Bs[kq + 0][row] = wa.x; Bs[kq + 1][row] = wa.y;
            Bs[kq + 2][row] = wa.z; Bs[kq + 3][row] = wa.w;
        }
        __syncthreads();

#pragma unroll
        for (int kk = 0; kk < 16; kk++) {
            float4 a0 = *(const float4*)&As[kk][ty * 8];
            float4 a1 = *(const float4*)&As[kk][ty * 8 + 4];
            float4 b0 = *(const float4*)&Bs[kk][tx * 8];
            float4 b1 = *(const float4*)&Bs[kk][tx * 8 + 4];
            u64 bb[4] = { pack2(b0.x, b0.y), pack2(b0.z, b0.w),
                          pack2(b1.x, b1.y), pack2(b1.z, b1.w) };
            float am[8] = { a0.x, a0.y, a0.z, a0.w, a1.x, a1.y, a1.z, a1.w };
#pragma unroll
            for (int m = 0; m < 8; m++) {
                u64 ad = pack2(am[m], am[m]);
#pragma unroll
                for (int n = 0; n < 4; n++) acc[m][n] = ffma2(ad, bb[n], acc[m][n]);
            }
        }
        __syncthreads();
    }

    const int nc = n0 + tx * 8;
    float4 bv0 = *(const float4*)(bih + nc);
    float4 bv1 = *(const float4*)(bih + nc + 4);
#pragma unroll
    for (int m = 0; m < 8; m++) {
        float2 r0 = unpack2(acc[m][0]), r1 = unpack2(acc[m][1]);
        float2 r2 = unpack2(acc[m][2]), r3 = unpack2(acc[m][3]);
        float* cp = C + (size_t)(m0 + ty * 8 + m) * 256 + nc;
        *(float4*)cp       = make_float4(r0.x + bv0.x, r0.y + bv0.y,
                                         r1.x + bv0.z, r1.y + bv0.w);
        *(float4*)(cp + 4) = make_float4(r2.x + bv1.x, r2.y + bv1.y,
                                         r3.x + bv1.z, r3.y + bv1.w);
    }
}

// ---------------------------------------------------------------------------
// Phase 2 (v4): own-outputs-as-k scan, TWO parity barriers, v4 st.async.
//
// Cluster of 2 CTAs per batch. CTA r owns outputs J_r = [r*128, r*128+128);
// its k-range is also J_r, so the h values it needs are the ones it computed
// itself (h never crosses the cluster). Thread tid computes the partial for
// output j = tid over k in J_r (W_hh[tid][J_r] in 64 packed f32x2 regs).
//
// Senders (j in peer's range) shfl-pack 4 partials/lane and ship 32 x
// st.async.v4 (data + complete_tx fused). Combiners wait ONE mbarrier
// (expect_tx = 512B), combine own+recv+xp+b, tanh, store h locally.
//
// Barrier[p] serves steps t = p (mod 2); it flips once per use, so the wait
// parity at step t is (t>>1)&1. Re-arm for t+2 is posted between wait(t) and
// __syncthreads(t), which provably happens-before the peer's t+2 sends:
//   peer send(t+2) >= peer sync(t+1) >= peer wait(t+1) >= our send(t+1)
//   >= our sync(t) >= our expect(t+2).
// This closes the expect/complete underflow race that hung R3.
// ---------------------------------------------------------------------------
__device__ __forceinline__ void mbar_wait_cluster(uint32_t addr, uint32_t parity) {
    asm volatile(
        "{\n\t"
        ".reg .pred P;\n\t"
        "LAB_W_%=:\n\t"
        "mbarrier.try_wait.parity.acquire.cluster.shared::cta.b64 P, [%0], %1, 0x989680;\n\t"
        "@P bra.uni LAB_D_%=;\n\t"
        "bra.uni LAB_W_%=;\n\t"
        "LAB_D_%=:\n\t"
        "}"
        :: "r"(addr), "r"(parity) : "memory");
}
__device__ __forceinline__ void mbar_expect(uint32_t addr, uint32_t bytes) {
    asm volatile("mbarrier.arrive.expect_tx.shared.b64 _, [%0], %1;"
                 :: "r"(addr), "r"(bytes) : "memory");
}

__global__ void __cluster_dims__(2, 1, 1) __launch_bounds__(256, 1)
rnn_scan_kernel(const float* __restrict__ Whh, const float* __restrict__ bhh,
                float* __restrict__ out)
{
    __shared__ __align__(16) float h_sm[2][128];     // own outputs = our k-range
    __shared__ __align__(16) float recv_sm[2][128];  // peer partials, parity buffered
    __shared__ __align__(16) u64 mbar[2];            // one barrier per step parity

    const int tid = threadIdx.x;
    uint32_t rank;
    asm("mov.u32 %0, %%cluster_ctarank;" : "=r"(rank));
    const int  batch      = blockIdx.x >> 1;
    const int  jl         = tid & 127;
    const bool is_combine = ((tid >> 7) == (int)rank);   // owns output j=tid
    const bool elected    = (tid == (int)rank * 128);
    const int  kbase      = (int)rank * 128;

    // --- W_hh[tid][kbase .. kbase+127] -> 64 packed f32x2 registers ---
    u64 w2[64];
    {
        const ulonglong2* wrow = (const ulonglong2*)(Whh + (size_t)tid * 256 + kbase);
#pragma unroll
        for (int i = 0; i < 32; i++) {
            ulonglong2 v = wrow[i];
            w2[2 * i] = v.x; w2[2 * i + 1] = v.y;
        }
    }

    // --- init ---
    if (tid < 128) { h_sm[0][tid] = 0.0f; h_sm[1][tid] = 0.0f; }
    uint32_t mbar_a0 = smem_u32(&mbar[0]);
    uint32_t mbar_a1 = smem_u32(&mbar[1]);
    if (tid == 0) {
        asm volatile("mbarrier.init.shared.b64 [%0], 1;" :: "r"(mbar_a0) : "memory");
        asm volatile("mbarrier.init.shared.b64 [%0], 1;" :: "r"(mbar_a1) : "memory");
    }
    __syncthreads();
    if (elected) {              // pre-arm phases for t=0 and t=1
        mbar_expect(mbar_a0, 512u);
        mbar_expect(mbar_a1, 512u);
    }
    asm volatile("barrier.cluster.arrive.aligned;" ::: "memory");
    asm volatile("barrier.cluster.wait.aligned;" ::: "memory");

    uint32_t recv_a = smem_u32(&recv_sm[0][0]);
    uint32_t peer = rank ^ 1u;
    uint32_t recv_peer, mbar_peer[2];
    asm("mapa.shared::cluster.u32 %0, %1, %2;" : "=r"(recv_peer)    : "r"(recv_a),  "r"(peer));
    asm("mapa.shared::cluster.u32 %0, %1, %2;" : "=r"(mbar_peer[0]) : "r"(mbar_a0), "r"(peer));
    asm("mapa.shared::cluster.u32 %0, %1, %2;" : "=r"(mbar_peer[1]) : "r"(mbar_a1), "r"(peer));

    float* outb = out + (size_t)batch * (1024 * 256) + tid;   // column j = tid
    const float bh = bhh[tid];
    float xp_next = is_combine ? outb[0] : 0.0f;

    for (int t = 0; t < 1024; t++) {
        const int p = t & 1;

        // --- partial for output j=tid over k in J_r (h local, broadcast LDS) ---
        const ulonglong2* h4 = (const ulonglong2*)&h_sm[p][0];
        u64 acc0 = 0ull, acc1 = 0ull;
#pragma unroll
        for (int i = 0; i < 16; i++) {
            ulonglong2 va = h4[2 * i];
            acc0 = ffma2(w2[4 * i],     va.x, acc0);
            acc1 = ffma2(w2[4 * i + 1], va.y, acc1);
            ulonglong2 vb = h4[2 * i + 1];
            acc0 = ffma2(w2[4 * i + 2], vb.x, acc0);
            acc1 = ffma2(w2[4 * i + 3], vb.y, acc1);
        }
        float2 a0 = unpack2(acc0), a1 = unpack2(acc1);
        const float s = (a0.x + a0.y) + (a1.x + a1.y);

        if (!is_combine) {
            // pack 4 partials/lane; 32 v4 st.async carry data + tx completion
            const float s1 = __shfl_down_sync(0xFFFFFFFFu, s, 1);
            const float s2 = __shfl_down_sync(0xFFFFFFFFu, s, 2);
            const float s3 = __shfl_down_sync(0xFFFFFFFFu, s, 3);
            if ((tid & 3) == 0) {
                uint32_t raddr = recv_peer + (uint32_t)((p << 7) + jl) * 4u;
                asm volatile(
                    "st.async.shared::cluster.mbarrier::complete_tx::bytes.v4.b32 "
                    "[%0], {%1, %2, %3, %4}, [%5];"
                    :: "r"(raddr),
                       "r"(__float_as_uint(s)),  "r"(__float_as_uint(s1)),
                       "r"(__float_as_uint(s2)), "r"(__float_as_uint(s3)),
                       "r"(mbar_peer[p]) : "memory");
            }
        } else {
            const float xp_cur = xp_next;
            // barrier[p] flips once every 2 steps -> parity = (t>>1)&1
            mbar_wait_cluster(p ? mbar_a1 : mbar_a0, (uint32_t)((t >> 1) & 1));
            // re-arm THIS barrier for step t+2 (before syncthreads: race-free)
            if (elected && t < 1022)
                mbar_expect(p ? mbar_a1 : mbar_a0, 512u);
            const float tot = s + recv_sm[p][jl] + xp_cur + bh;
            const float h = tanh_acc(tot);
            h_sm[p ^ 1][jl] = h;                       // local h for next step
            outb[(size_t)t * 256] = h;                 // final output
            if (t < 1023) xp_next = __ldg(outb + (size_t)(t + 1) * 256);
        }
        __syncthreads();   // h_{t+1} visible to senders+combiners before next FMA
    }

    // keep smem alive until peer's in-flight st.async complete
    asm volatile("barrier.cluster.arrive.aligned;" ::: "memory");
    asm volatile("barrier.cluster.wait.aligned;" ::: "memory");
}

// ---------------------------------------------------------------------------
// Harness entry. Inputs: x, W_ih, W_hh, b_ih, b_hh. Output fp32 [B,T,H].
// x_proj is materialized into d_out, then overwritten in place by h_t.
// ---------------------------------------------------------------------------
extern "C" void kernel_launch(void* const* d_in, const int* in_sizes, int n_in,
                              void* d_out, int out_size)
{
    const float* x   = (const float*)d_in[0];
    const float* Wih = (const float*)d_in[1];
    const float* Whh = (const float*)d_in[2];
    const float* bih = (const float*)d_in[3];
    const float* bhh = (const float*)d_in[4];
    float* out = (float*)d_out;

    dim3 g1(2, 512);
    xproj_kernel<<<g1, 256>>>(x, Wih, bih, out);

    rnn_scan_kernel<<<128, 256>>>(Whh, bhh, out);
}